// round 2
// baseline (speedup 1.0000x reference)
#include <cuda_runtime.h>
#include <cuda_bf16.h>

// Problem dims
#define BB   128
#define TT   512
#define HH   256
#define H2   512
#define LIN  200
#define FEAT 582
#define FPAD 584
#define G4   1024
#define SP   58
#define KV   768   // 256 + 512

// ---------------- device scratch (globals: allocation-free rule) ----------------
__device__ float g_csum [BB * TT * H2];          // exclusive prefix sums  (128 MB)
__device__ float g_feats[BB * TT * FPAD];        // features               (146 MB)
__device__ float g_z    [BB * TT * LIN];         // tanh(fc) output        ( 50 MB)
__device__ float g_G0   [BB * TT * G4];          // z@W_ih^T + biases      (256 MB)
__device__ float g_hs   [BB * TT * HH];          // LSTM hidden outputs    ( 64 MB)
__device__ float g_h    [2 * BB * HH];           // double-buffered h state
__device__ int   g_lastsep[BB * TT];

// grid barrier state
__device__ unsigned g_bar_count = 0;
__device__ volatile unsigned g_bar_gen = 0;

__device__ __forceinline__ float sigf(float x) { return 1.f / (1.f + __expf(-x)); }
__device__ __forceinline__ float tanhfast(float x) {
    float e = __expf(2.f * x);
    return 1.f - 2.f / (e + 1.f);
}

// ---------------- kernel 1: prefix sums + last-sep scan ----------------
__global__ void __launch_bounds__(512) prep_k(const float* __restrict__ enc,
                                              const int* __restrict__ sep) {
    const int b = blockIdx.x;
    const int ch = threadIdx.x;
    const float* e = enc + (long long)b * TT * H2 + ch;
    float* cs = g_csum + (long long)b * TT * H2 + ch;
    float run = 0.f;
    int cm = 0;
    const int* sp = sep + b * TT;
    int* ls = g_lastsep + b * TT;
    for (int t = 0; t < TT; t++) {
        cs[t * H2] = run;
        run += e[t * H2];
        if (ch == 0) {
            ls[t] = cm;
            if (sp[t] > 0) cm = t;   // cummax(sep_pos) with monotone t
        }
    }
}

// ---------------- kernel 2: build features ----------------
__global__ void __launch_bounds__(128) feats_k(const int* __restrict__ pos_ids,
                                               const float* __restrict__ pos_emb,
                                               const float* __restrict__ wordlen_emb) {
    const int m = blockIdx.x;             // b*T + t
    const int b = m >> 9;
    const int t = m & (TT - 1);
    const int ls = g_lastsep[m];
    int wlen = t - ls; if (wlen < 1) wlen = 1;
    const int wid = (wlen < 7) ? wlen : 7;
    const int lp = pos_ids[b * TT + ls];
    const float inv = 1.0f / (float)wlen;
    float* f = g_feats + (long long)m * FPAD;
    const float* ct = g_csum + ((long long)b * TT + t) * H2;
    const float* cs = g_csum + ((long long)b * TT + ls) * H2;
    for (int i = threadIdx.x; i < FPAD; i += 128) {
        float v;
        if (i < 50)       v = pos_emb[lp * 50 + i];
        else if (i < 562) { int k = i - 50; v = (ct[k] - cs[k]) * inv; }
        else if (i < 582) v = wordlen_emb[wid * 20 + (i - 562)];
        else              v = 0.f;
        f[i] = v;
    }
}

// ---------------- generic fp32 GEMM: C[M,N] = A[M,K] * B[N,K]^T (+epilogue) ----
// MODE 1: fc      (bias1=fc_b, tanh, zero at t==0)
// MODE 2: ih      (bias1=b_ih, bias2=b_hh)
// MODE 3: combine (A fused hs|enc, mask epilogue)
template<int MODE, bool VECB>
__global__ void __launch_bounds__(256) gemm_k(
    const float* __restrict__ A, const float* __restrict__ Bm,
    const float* __restrict__ bias1, const float* __restrict__ bias2,
    const float* __restrict__ enc, const int* __restrict__ length,
    float* __restrict__ C, int N, int K, int lda, int ldb, int ldc)
{
    __shared__ float As[16 * 68];
    __shared__ float Bs[16 * 68];
    const int m0 = blockIdx.x * 64;
    const int n0 = blockIdx.y * 64;
    const int tid = threadIdx.x;
    const int lrow = tid >> 2;
    const int lk = (tid & 3) * 4;
    const int ty = tid >> 4, tx = tid & 15;

    float acc[4][4];
    #pragma unroll
    for (int i = 0; i < 4; i++)
        #pragma unroll
        for (int q = 0; q < 4; q++) acc[i][q] = 0.f;

    const int nkt = (K + 15) >> 4;

    auto loadA4 = [&](int kt, float4& r) {
        const int k = kt * 16 + lk;
        const int m = m0 + lrow;
        if (k + 3 < K) {
            if (MODE == 3) {
                const float* src = (k < 256) ? (A + (long long)m * 256 + k)
                                             : (enc + (long long)m * 512 + (k - 256));
                r = *reinterpret_cast<const float4*>(src);
            } else {
                r = *reinterpret_cast<const float4*>(A + (long long)m * lda + k);
            }
        } else {
            float tmp[4];
            #pragma unroll
            for (int i = 0; i < 4; i++) {
                const int kk = k + i;
                float v = 0.f;
                if (kk < K) {
                    if (MODE == 3) v = (kk < 256) ? A[(long long)m * 256 + kk]
                                                  : enc[(long long)m * 512 + kk - 256];
                    else v = A[(long long)m * lda + kk];
                }
                tmp[i] = v;
            }
            r = make_float4(tmp[0], tmp[1], tmp[2], tmp[3]);
        }
    };
    auto loadB4 = [&](int kt, float4& r) {
        const int k = kt * 16 + lk;
        const int n = n0 + lrow;
        if (VECB && n < N && k + 3 < K) {
            r = *reinterpret_cast<const float4*>(Bm + (long long)n * ldb + k);
        } else {
            float tmp[4];
            #pragma unroll
            for (int i = 0; i < 4; i++) {
                const int kk = k + i;
                tmp[i] = (n < N && kk < K) ? Bm[(long long)n * ldb + kk] : 0.f;
            }
            r = make_float4(tmp[0], tmp[1], tmp[2], tmp[3]);
        }
    };

    float4 ra, rb;
    loadA4(0, ra); loadB4(0, rb);
    for (int kt = 0; kt < nkt; kt++) {
        As[(lk + 0) * 68 + lrow] = ra.x;
        As[(lk + 1) * 68 + lrow] = ra.y;
        As[(lk + 2) * 68 + lrow] = ra.z;
        As[(lk + 3) * 68 + lrow] = ra.w;
        Bs[(lk + 0) * 68 + lrow] = rb.x;
        Bs[(lk + 1) * 68 + lrow] = rb.y;
        Bs[(lk + 2) * 68 + lrow] = rb.z;
        Bs[(lk + 3) * 68 + lrow] = rb.w;
        __syncthreads();
        float4 na, nb;
        if (kt + 1 < nkt) { loadA4(kt + 1, na); loadB4(kt + 1, nb); }
        #pragma unroll
        for (int kk = 0; kk < 16; kk++) {
            const float4 a = *reinterpret_cast<const float4*>(&As[kk * 68 + ty * 4]);
            const float4 b = *reinterpret_cast<const float4*>(&Bs[kk * 68 + tx * 4]);
            acc[0][0] += a.x * b.x; acc[0][1] += a.x * b.y; acc[0][2] += a.x * b.z; acc[0][3] += a.x * b.w;
            acc[1][0] += a.y * b.x; acc[1][1] += a.y * b.y; acc[1][2] += a.y * b.z; acc[1][3] += a.y * b.w;
            acc[2][0] += a.z * b.x; acc[2][1] += a.z * b.y; acc[2][2] += a.z * b.z; acc[2][3] += a.z * b.w;
            acc[3][0] += a.w * b.x; acc[3][1] += a.w * b.y; acc[3][2] += a.w * b.z; acc[3][3] += a.w * b.w;
        }
        __syncthreads();
        ra = na; rb = nb;
    }

    #pragma unroll
    for (int i = 0; i < 4; i++) {
        const int m = m0 + ty * 4 + i;
        const int t = m & (TT - 1);
        #pragma unroll
        for (int q = 0; q < 4; q++) {
            const int n = n0 + tx * 4 + q;
            if (n >= N) continue;
            float v = acc[i][q];
            if (MODE == 1) {
                v = tanhfast(v + bias1[n]);
                if (t == 0) v = 0.f;
            } else if (MODE == 2) {
                v += bias1[n] + bias2[n];
            } else {
                const int b = m >> 9;
                if (t >= length[b]) v = 0.f;
                else if (t == 0 && n == 0) v = -1e30f;
            }
            C[(long long)m * ldc + n] = v;
        }
    }
}

// ---------------- grid barrier ----------------
#define NB_LSTM 128
__device__ __forceinline__ void grid_sync(unsigned& gen) {
    __threadfence();
    __syncthreads();
    if (threadIdx.x == 0) {
        const unsigned prev = atomicAdd(&g_bar_count, 1u);
        if (prev == NB_LSTM - 1u) {
            g_bar_count = 0u;
            __threadfence();
            g_bar_gen = gen + 1u;
        } else {
            while (g_bar_gen == gen) { }
            __threadfence();
        }
    }
    __syncthreads();
    gen++;
}

// ---------------- kernel: persistent LSTM recurrence ----------------
// 128 blocks: blockIdx = bt(0..3)*32 + ht(0..31). Block tile: 32 batches x 8 hidden.
// W_hh slice (4 gates x 8 rows x 256) cached in smem for all 512 steps.
__global__ void __launch_bounds__(128, 1) lstm_k(const float* __restrict__ W_hh) {
    extern __shared__ float sm[];
    float* Wsm = sm;                 // [32][260]
    float* Hsm = sm + 32 * 260;      // [32][260]
    const int bt = blockIdx.x >> 5;
    const int ht = blockIdx.x & 31;
    const int tid = threadIdx.x;
    const int bg = tid >> 3, jj = tid & 7;
    const int b0 = bt * 32 + bg * 2;
    const int j  = ht * 8 + jj;

    // load W slice: row r: gate g = r>>3, hidden offset r&7
    for (int idx = tid; idx < 2048; idx += 128) {
        const int r = idx >> 6;
        const int k4 = idx & 63;
        const int g = r >> 3, hr = r & 7;
        const float4 w = reinterpret_cast<const float4*>(W_hh)[(g * 256 + ht * 8 + hr) * 64 + k4];
        *reinterpret_cast<float4*>(&Wsm[r * 260 + k4 * 4]) = w;
    }
    // init h buffer 0 (exactly our owned entries across all blocks)
    g_h[b0 * HH + j] = 0.f;
    g_h[(b0 + 1) * HH + j] = 0.f;
    float c0 = 0.f, c1 = 0.f;
    unsigned gen = g_bar_gen;
    grid_sync(gen);

    const float* Wr0 = &Wsm[(jj     ) * 260];
    const float* Wr1 = &Wsm[( 8 + jj) * 260];
    const float* Wr2 = &Wsm[(16 + jj) * 260];
    const float* Wr3 = &Wsm[(24 + jj) * 260];

    for (int t = 0; t < TT; t++) {
        // init accumulators from precomputed z@W_ih + biases
        const float* G0a = g_G0 + ((long long)(b0 * TT + t)) * G4 + j;
        const float* G0b = g_G0 + ((long long)((b0 + 1) * TT + t)) * G4 + j;
        float ai0 = G0a[0], af0 = G0a[256], ag0 = G0a[512], ao0 = G0a[768];
        float ai1 = G0b[0], af1 = G0b[256], ag1 = G0b[512], ao1 = G0b[768];

        // stage h tile [32 x 256] into smem
        const float* hb = g_h + (t & 1) * (BB * HH) + bt * 32 * HH;
        for (int idx = tid; idx < 2048; idx += 128) {
            const int r = idx >> 6, k4 = idx & 63;
            *reinterpret_cast<float4*>(&Hsm[r * 260 + k4 * 4]) =
                reinterpret_cast<const float4*>(hb)[r * 64 + k4];
        }
        __syncthreads();

        const float* H0 = &Hsm[(bg * 2) * 260];
        const float* H1 = H0 + 260;
        #pragma unroll 8
        for (int k4 = 0; k4 < 64; k4++) {
            const float4 h0 = *reinterpret_cast<const float4*>(&H0[k4 * 4]);
            const float4 h1 = *reinterpret_cast<const float4*>(&H1[k4 * 4]);
            float4 w;
            w = *reinterpret_cast<const float4*>(&Wr0[k4 * 4]);
            ai0 += h0.x * w.x + h0.y * w.y + h0.z * w.z + h0.w * w.w;
            ai1 += h1.x * w.x + h1.y * w.y + h1.z * w.z + h1.w * w.w;
            w = *reinterpret_cast<const float4*>(&Wr1[k4 * 4]);
            af0 += h0.x * w.x + h0.y * w.y + h0.z * w.z + h0.w * w.w;
            af1 += h1.x * w.x + h1.y * w.y + h1.z * w.z + h1.w * w.w;
            w = *reinterpret_cast<const float4*>(&Wr2[k4 * 4]);
            ag0 += h0.x * w.x + h0.y * w.y + h0.z * w.z + h0.w * w.w;
            ag1 += h1.x * w.x + h1.y * w.y + h1.z * w.z + h1.w * w.w;
            w = *reinterpret_cast<const float4*>(&Wr3[k4 * 4]);
            ao0 += h0.x * w.x + h0.y * w.y + h0.z * w.z + h0.w * w.w;
            ao1 += h1.x * w.x + h1.y * w.y + h1.z * w.z + h1.w * w.w;
        }
        // gates (torch order i, f, g, o)
        const float i0 = sigf(ai0), f0 = sigf(af0), gg0 = tanhfast(ag0), o0 = sigf(ao0);
        c0 = f0 * c0 + i0 * gg0;
        const float hv0 = o0 * tanhfast(c0);
        const float i1 = sigf(ai1), f1 = sigf(af1), gg1 = tanhfast(ag1), o1 = sigf(ao1);
        c1 = f1 * c1 + i1 * gg1;
        const float hv1 = o1 * tanhfast(c1);

        g_hs[((long long)(b0 * TT + t)) * HH + j] = hv0;
        g_hs[((long long)((b0 + 1) * TT + t)) * HH + j] = hv1;
        float* hn = g_h + ((t + 1) & 1) * (BB * HH);
        hn[b0 * HH + j] = hv0;
        hn[(b0 + 1) * HH + j] = hv1;
        grid_sync(gen);
    }
}

// ---------------- host launch ----------------
extern "C" void kernel_launch(void* const* d_in, const int* in_sizes, int n_in,
                              void* d_out, int out_size) {
    const float* enc         = (const float*)d_in[0];
    const int*   sep_mask    = (const int*)d_in[1];
    const int*   pos_ids     = (const int*)d_in[2];
    const int*   length      = (const int*)d_in[3];
    const float* pos_emb     = (const float*)d_in[4];
    const float* wordlen_emb = (const float*)d_in[5];
    const float* fc_W        = (const float*)d_in[6];
    const float* fc_b        = (const float*)d_in[7];
    const float* W_ih        = (const float*)d_in[8];
    const float* W_hh        = (const float*)d_in[9];
    const float* b_ih        = (const float*)d_in[10];
    const float* b_hh        = (const float*)d_in[11];
    const float* combine_W   = (const float*)d_in[12];
    float* out = (float*)d_out;

    float* d_feats; cudaGetSymbolAddress((void**)&d_feats, g_feats);
    float* d_z;     cudaGetSymbolAddress((void**)&d_z, g_z);
    float* d_G0;    cudaGetSymbolAddress((void**)&d_G0, g_G0);
    float* d_hs;    cudaGetSymbolAddress((void**)&d_hs, g_hs);

    prep_k<<<BB, 512>>>(enc, sep_mask);
    feats_k<<<BB * TT, 128>>>(pos_ids, pos_emb, wordlen_emb);

    // GEMM1: z = tanh(feats @ fc_W^T + fc_b)   M=65536 N=200 K=582
    gemm_k<1, false><<<dim3(1024, 4), 256>>>(
        d_feats, fc_W, fc_b, nullptr, nullptr, nullptr, d_z,
        LIN, FEAT, FPAD, FEAT, LIN);

    // GEMM2: G0 = z @ W_ih^T + b_ih + b_hh     M=65536 N=1024 K=200
    gemm_k<2, true><<<dim3(1024, 16), 256>>>(
        d_z, W_ih, b_ih, b_hh, nullptr, nullptr, d_G0,
        G4, LIN, LIN, LIN, G4);

    // LSTM recurrence (persistent, grid-synced)
    const int lstm_smem = 2 * 32 * 260 * sizeof(float);
    cudaFuncSetAttribute(lstm_k, cudaFuncAttributeMaxDynamicSharedMemorySize, lstm_smem);
    lstm_k<<<NB_LSTM, 128, lstm_smem>>>(W_hh);

    // GEMM3: logits = [hs|enc] @ combine_W^T + mask   M=65536 N=58 K=768
    gemm_k<3, true><<<dim3(1024, 1), 256>>>(
        d_hs, combine_W, nullptr, nullptr, enc, length, out,
        SP, KV, 0, KV, SP);
}